// round 1
// baseline (speedup 1.0000x reference)
#include <cuda_runtime.h>
#include <math.h>

// Problem constants
#define BATCH 2
#define CTX   2048
#define DM    1024      // model dim (D_IN == D_OUT)
#define NH    16
#define HD    64
#define BT    (BATCH*CTX)   // 4096 rows

// -------- scratch (device globals; no allocation allowed) --------
__device__ float g_Q[BT * DM];
__device__ float g_K[BT * DM];
__device__ float g_V[BT * DM];
__device__ float g_C[BT * DM];

// ============================================================================
// SGEMM: C[M,N] = A[M,K] @ B[K,N] (+ bias). BM=BN=128, BK=16, 8x8 per thread.
// ============================================================================
__global__ __launch_bounds__(256) void sgemm128(
    const float* __restrict__ A, const float* __restrict__ Bm,
    const float* __restrict__ bias, float* __restrict__ C,
    int M, int N, int K)
{
    __shared__ __align__(16) float As[16][132];   // transposed: As[k][m]
    __shared__ __align__(16) float Bs[16][128];   // Bs[k][n]

    const int tid = threadIdx.x;
    const int tx = tid & 15;       // 0..15 -> 8 cols each
    const int ty = tid >> 4;       // 0..15 -> 8 rows each
    const int row0 = blockIdx.y * 128;
    const int col0 = blockIdx.x * 128;

    float acc[8][8];
    #pragma unroll
    for (int i = 0; i < 8; i++)
        #pragma unroll
        for (int j = 0; j < 8; j++) acc[i][j] = 0.f;

    const float4* A4 = (const float4*)A;
    const float4* B4 = (const float4*)Bm;

    for (int k0 = 0; k0 < K; k0 += 16) {
        // Load A tile: 128 rows x 16 k = 512 float4, transpose into As
        #pragma unroll
        for (int i = 0; i < 2; i++) {
            int idx = tid + i * 256;          // 0..511
            int r = idx >> 2;                 // 0..127
            int c = idx & 3;                  // float4 within 16 k
            float4 v = A4[((size_t)(row0 + r) * K + k0) / 4 + c];
            As[4*c + 0][r] = v.x;
            As[4*c + 1][r] = v.y;
            As[4*c + 2][r] = v.z;
            As[4*c + 3][r] = v.w;
        }
        // Load B tile: 16 rows x 128 cols = 512 float4
        #pragma unroll
        for (int i = 0; i < 2; i++) {
            int idx = tid + i * 256;
            int r = idx >> 5;                 // 0..15
            int c = idx & 31;                 // float4 col
            float4 v = B4[((size_t)(k0 + r) * N + col0) / 4 + c];
            *(float4*)&Bs[r][4*c] = v;
        }
        __syncthreads();

        #pragma unroll
        for (int k = 0; k < 16; k++) {
            float a[8], b[8];
            *(float4*)&a[0] = *(const float4*)&As[k][ty*8];
            *(float4*)&a[4] = *(const float4*)&As[k][ty*8 + 4];
            *(float4*)&b[0] = *(const float4*)&Bs[k][tx*8];
            *(float4*)&b[4] = *(const float4*)&Bs[k][tx*8 + 4];
            #pragma unroll
            for (int i = 0; i < 8; i++)
                #pragma unroll
                for (int j = 0; j < 8; j++)
                    acc[i][j] += a[i] * b[j];
        }
        __syncthreads();
    }

    #pragma unroll
    for (int i = 0; i < 8; i++) {
        int r = row0 + ty*8 + i;
        #pragma unroll
        for (int j4 = 0; j4 < 2; j4++) {
            int c = col0 + tx*8 + j4*4;
            float4 v;
            v.x = acc[i][j4*4+0]; v.y = acc[i][j4*4+1];
            v.z = acc[i][j4*4+2]; v.w = acc[i][j4*4+3];
            if (bias) {
                v.x += bias[c+0]; v.y += bias[c+1];
                v.z += bias[c+2]; v.w += bias[c+3];
            }
            *(float4*)&C[(size_t)r * N + c] = v;
        }
    }
}

// ============================================================================
// Flash attention (causal, fp32). QT=128 q rows per block, KT=64 keys/tile.
// Grid: (CTX/128, NH, BATCH). 256 threads: tx(16) x 4 key-cols, ty(16) x 8 q-rows.
// Dynamic smem layout (floats):
//   Qs[64][132]  (d-major, scaled by 1/sqrt(hd))
//   Ks[64][68]   (d-major)
//   Vs[64][68]   (k-major)
//   Ps[64][132]  (k-major: Ps[k][q])
// ============================================================================
#define QT 128
#define KT 64
#define QS_LD 132
#define KS_LD 68
#define VS_LD 68
#define PS_LD 132
#define SMEM_FLOATS (64*QS_LD + 64*KS_LD + 64*VS_LD + 64*PS_LD)  // 25600 -> 102400 B

__global__ __launch_bounds__(256) void flash_attn(
    const float* __restrict__ Q, const float* __restrict__ K,
    const float* __restrict__ V, float* __restrict__ O)
{
    extern __shared__ __align__(16) float sm[];
    float* Qs = sm;                          // [64][132]
    float* Ks = Qs + 64 * QS_LD;             // [64][68]
    float* Vs = Ks + 64 * KS_LD;             // [64][68]
    float* Ps = Vs + 64 * VS_LD;             // [64][132]

    const int tid = threadIdx.x;
    const int tx = tid & 15;                 // key-col group (4 cols)
    const int ty = tid >> 4;                 // q-row group (8 rows)
    const int q0 = blockIdx.x * QT;
    const int h  = blockIdx.y;
    const int b  = blockIdx.z;

    const float scale = 0.125f;              // 1/sqrt(64)

    const float4* Q4 = (const float4*)Q;
    const float4* K4 = (const float4*)K;
    const float4* V4 = (const float4*)V;

    // ---- Load Q tile (transposed, pre-scaled): 2048 float4 ----
    #pragma unroll
    for (int i = 0; i < 8; i++) {
        int idx = tid + i * 256;             // 0..2047
        int q = idx >> 4;                    // 0..127
        int c4 = idx & 15;                   // float4 along d
        float4 v = Q4[((size_t)((b*CTX) + q0 + q) * DM + h*HD) / 4 + c4];
        Qs[(4*c4+0)*QS_LD + q] = v.x * scale;
        Qs[(4*c4+1)*QS_LD + q] = v.y * scale;
        Qs[(4*c4+2)*QS_LD + q] = v.z * scale;
        Qs[(4*c4+3)*QS_LD + q] = v.w * scale;
    }

    // online softmax state
    float m[8], l[8], o[8][4];
    #pragma unroll
    for (int i = 0; i < 8; i++) {
        m[i] = -INFINITY; l[i] = 0.f;
        #pragma unroll
        for (int j = 0; j < 4; j++) o[i][j] = 0.f;
    }

    const int nkv = q0 / KT + 2;             // tiles fully/partially below diagonal

    for (int t = 0; t < nkv; t++) {
        const int kb = t * KT;

        // ---- Load K (transposed) and V tiles: 1024 float4 each ----
        #pragma unroll
        for (int i = 0; i < 4; i++) {
            int idx = tid + i * 256;         // 0..1023
            int kk = idx >> 4;               // 0..63
            int c4 = idx & 15;
            float4 v = K4[((size_t)((b*CTX) + kb + kk) * DM + h*HD) / 4 + c4];
            Ks[(4*c4+0)*KS_LD + kk] = v.x;
            Ks[(4*c4+1)*KS_LD + kk] = v.y;
            Ks[(4*c4+2)*KS_LD + kk] = v.z;
            Ks[(4*c4+3)*KS_LD + kk] = v.w;
            float4 w = V4[((size_t)((b*CTX) + kb + kk) * DM + h*HD) / 4 + c4];
            *(float4*)&Vs[kk*VS_LD + 4*c4] = w;
        }
        __syncthreads();

        // ---- S = Qs^T @ Ks  (per-thread 8x4) ----
        float s[8][4];
        #pragma unroll
        for (int i = 0; i < 8; i++)
            #pragma unroll
            for (int j = 0; j < 4; j++) s[i][j] = 0.f;

        #pragma unroll 8
        for (int d = 0; d < HD; d++) {
            float a[8], bb[4];
            *(float4*)&a[0] = *(const float4*)&Qs[d*QS_LD + 8*ty];
            *(float4*)&a[4] = *(const float4*)&Qs[d*QS_LD + 8*ty + 4];
            *(float4*)&bb[0] = *(const float4*)&Ks[d*KS_LD + 4*tx];
            #pragma unroll
            for (int i = 0; i < 8; i++)
                #pragma unroll
                for (int j = 0; j < 4; j++)
                    s[i][j] += a[i] * bb[j];
        }

        // ---- causal mask (only for the 2 diagonal tiles) ----
        if (kb + KT - 1 > q0) {
            #pragma unroll
            for (int i = 0; i < 8; i++) {
                int r = q0 + 8*ty + i;
                #pragma unroll
                for (int j = 0; j < 4; j++) {
                    if (kb + 4*tx + j > r) s[i][j] = -1e30f;
                }
            }
        }

        // ---- online softmax update ----
        #pragma unroll
        for (int i = 0; i < 8; i++) {
            float rm = s[i][0];
            #pragma unroll
            for (int j = 1; j < 4; j++) rm = fmaxf(rm, s[i][j]);
            // reduce max over 16 threads covering the row
            #pragma unroll
            for (int off = 1; off < 16; off <<= 1)
                rm = fmaxf(rm, __shfl_xor_sync(0xffffffffu, rm, off));
            float m_new = fmaxf(m[i], rm);
            float corr = __expf(m[i] - m_new);
            float rs = 0.f;
            #pragma unroll
            for (int j = 0; j < 4; j++) {
                float p = __expf(s[i][j] - m_new);
                s[i][j] = p;                 // s becomes P
                rs += p;
            }
            #pragma unroll
            for (int off = 1; off < 16; off <<= 1)
                rs += __shfl_xor_sync(0xffffffffu, rs, off);
            l[i] = l[i] * corr + rs;
            m[i] = m_new;
            #pragma unroll
            for (int j = 0; j < 4; j++) o[i][j] *= corr;
        }

        // ---- write P (k-major) ----
        #pragma unroll
        for (int i = 0; i < 8; i++) {
            int q = 8*ty + i;
            #pragma unroll
            for (int j = 0; j < 4; j++)
                Ps[(4*tx + j)*PS_LD + q] = s[i][j];
        }
        __syncthreads();

        // ---- O += P @ V ----
        #pragma unroll 8
        for (int k = 0; k < KT; k++) {
            float a[8], bb[4];
            *(float4*)&a[0] = *(const float4*)&Ps[k*PS_LD + 8*ty];
            *(float4*)&a[4] = *(const float4*)&Ps[k*PS_LD + 8*ty + 4];
            *(float4*)&bb[0] = *(const float4*)&Vs[k*VS_LD + 4*tx];
            #pragma unroll
            for (int i = 0; i < 8; i++)
                #pragma unroll
                for (int j = 0; j < 4; j++)
                    o[i][j] += a[i] * bb[j];
        }
        __syncthreads();
    }

    // ---- normalize + write ctx [B,T,H*HD] ----
    #pragma unroll
    for (int i = 0; i < 8; i++) {
        float inv = 1.f / l[i];
        float4 v;
        v.x = o[i][0] * inv; v.y = o[i][1] * inv;
        v.z = o[i][2] * inv; v.w = o[i][3] * inv;
        int r = q0 + 8*ty + i;
        *(float4*)&O[(size_t)((b*CTX) + r) * DM + h*HD + 4*tx] = v;
    }
}

// ============================================================================
// launch
// ============================================================================
extern "C" void kernel_launch(void* const* d_in, const int* in_sizes, int n_in,
                              void* d_out, int out_size)
{
    const float* x  = (const float*)d_in[0];
    const float* Wq = (const float*)d_in[1];
    const float* Wk = (const float*)d_in[2];
    const float* Wv = (const float*)d_in[3];
    const float* Wo = (const float*)d_in[4];
    const float* bo = (const float*)d_in[5];
    float* out = (float*)d_out;

    float *Qp, *Kp, *Vp, *Cp;
    cudaGetSymbolAddress((void**)&Qp, g_Q);
    cudaGetSymbolAddress((void**)&Kp, g_K);
    cudaGetSymbolAddress((void**)&Vp, g_V);
    cudaGetSymbolAddress((void**)&Cp, g_C);

    cudaFuncSetAttribute(flash_attn, cudaFuncAttributeMaxDynamicSharedMemorySize,
                         SMEM_FLOATS * (int)sizeof(float));

    dim3 gblk(256);
    dim3 ggrid(DM / 128, BT / 128);   // (8, 32)

    sgemm128<<<ggrid, gblk>>>(x, Wq, nullptr, Qp, BT, DM, DM);
    sgemm128<<<ggrid, gblk>>>(x, Wk, nullptr, Kp, BT, DM, DM);
    sgemm128<<<ggrid, gblk>>>(x, Wv, nullptr, Vp, BT, DM, DM);

    dim3 fgrid(CTX / QT, NH, BATCH);  // (16, 16, 2)
    flash_attn<<<fgrid, 256, SMEM_FLOATS * sizeof(float)>>>(Qp, Kp, Vp, Cp);

    sgemm128<<<ggrid, gblk>>>(Cp, Wo, bo, out, BT, DM, DM);
}

// round 2
// speedup vs baseline: 2.8151x; 2.8151x over previous
#include <cuda_runtime.h>
#include <math.h>

#define BATCH 2
#define CTX   2048
#define DM    1024
#define NH    16
#define HD    64
#define BT    (BATCH*CTX)   // 4096

// ---------------- scratch (device globals; no allocation allowed) ----------
__device__ float g_Q[BT * DM];
__device__ float g_K[BT * DM];
__device__ float g_V[BT * DM];
__device__ float g_C[BT * DM];
__device__ float g_Xr[BT * DM];
__device__ float g_Wr[4 * DM * DM];

// ---------------- helpers ---------------------------------------------------
__device__ __forceinline__ float rna(float x) {
    unsigned u;
    asm("cvt.rna.tf32.f32 %0, %1;" : "=r"(u) : "f"(x));
    return __uint_as_float(u);
}

__device__ __forceinline__ void mma_tf32(float* d, const unsigned* a, unsigned b0, unsigned b1) {
    asm volatile(
        "mma.sync.aligned.m16n8k8.row.col.f32.tf32.tf32.f32 "
        "{%0,%1,%2,%3}, {%4,%5,%6,%7}, {%8,%9}, {%0,%1,%2,%3};"
        : "+f"(d[0]), "+f"(d[1]), "+f"(d[2]), "+f"(d[3])
        : "r"(a[0]), "r"(a[1]), "r"(a[2]), "r"(a[3]),
          "r"(b0), "r"(b1));
}

__device__ __forceinline__ void cp16(float* s, const float* g) {
    unsigned sa = (unsigned)__cvta_generic_to_shared(s);
    asm volatile("cp.async.ca.shared.global [%0], [%1], 16;" :: "r"(sa), "l"(g));
}

// ---------------- pre-round inputs to tf32 ----------------------------------
__global__ __launch_bounds__(256) void round_k(const float4* __restrict__ in,
                                               float4* __restrict__ out, int n4) {
    int i = blockIdx.x * 256 + threadIdx.x;
    if (i < n4) {
        float4 v = in[i];
        v.x = rna(v.x); v.y = rna(v.y); v.z = rna(v.z); v.w = rna(v.w);
        out[i] = v;
    }
}

// ============================================================================
// tf32 GEMM: C[M=4096, N=1024] = A @ B (+bias). BM=BN=128, BK=32.
// 256 threads = 8 warps (4 m x 2 n), warp tile 32x64, mma m16n8k8.
// ============================================================================
#define AS_LD 36
#define BS_LD 136
#define AS_SZ (128 * AS_LD)
#define BS_SZ (32 * BS_LD)
#define GEMM_SMEM ((2 * AS_SZ + 2 * BS_SZ) * (int)sizeof(float))

__global__ __launch_bounds__(256) void gemm_tf32(
    const float* __restrict__ A, const float* __restrict__ B,
    const float* __restrict__ bias, float* __restrict__ C)
{
    extern __shared__ float smg[];
    float* As = smg;
    float* Bs = smg + 2 * AS_SZ;

    const int tid = threadIdx.x;
    const int lane = tid & 31, wid = tid >> 5;
    const int g = lane >> 2, t = lane & 3;
    const int wm = wid & 3, wn = wid >> 2;
    const int row0 = blockIdx.y * 128, col0 = blockIdx.x * 128;

    float acc[2][8][4];
    #pragma unroll
    for (int mt = 0; mt < 2; mt++)
        #pragma unroll
        for (int nt = 0; nt < 8; nt++)
            #pragma unroll
            for (int r = 0; r < 4; r++) acc[mt][nt][r] = 0.f;

    auto issue = [&](int k0, int buf) {
        float* ab = As + buf * AS_SZ;
        float* bb = Bs + buf * BS_SZ;
        #pragma unroll
        for (int i = 0; i < 4; i++) {
            int idx = tid + i * 256;
            int r = idx >> 3, c = idx & 7;
            cp16(ab + r * AS_LD + 4 * c, A + (size_t)(row0 + r) * DM + k0 + 4 * c);
        }
        #pragma unroll
        for (int i = 0; i < 4; i++) {
            int idx = tid + i * 256;
            int r = idx >> 5, c = idx & 31;
            cp16(bb + r * BS_LD + 4 * c, B + (size_t)(k0 + r) * DM + col0 + 4 * c);
        }
        asm volatile("cp.async.commit_group;");
    };

    issue(0, 0);
    const int NT = DM / 32;   // 32 k-tiles
    for (int it = 0; it < NT; ++it) {
        if (it + 1 < NT) {
            issue((it + 1) * 32, (it + 1) & 1);
            asm volatile("cp.async.wait_group 1;");
        } else {
            asm volatile("cp.async.wait_group 0;");
        }
        __syncthreads();

        const float* ab = As + (it & 1) * AS_SZ;
        const float* bb = Bs + (it & 1) * BS_SZ;
        #pragma unroll
        for (int ks = 0; ks < 4; ks++) {
            unsigned a[2][4];
            #pragma unroll
            for (int mt = 0; mt < 2; mt++) {
                const float* ap = ab + (wm * 32 + mt * 16 + g) * AS_LD + ks * 8 + t;
                a[mt][0] = __float_as_uint(ap[0]);
                a[mt][1] = __float_as_uint(ap[8 * AS_LD]);
                a[mt][2] = __float_as_uint(ap[4]);
                a[mt][3] = __float_as_uint(ap[8 * AS_LD + 4]);
            }
            #pragma unroll
            for (int nt = 0; nt < 8; nt++) {
                const float* bp = bb + (ks * 8 + t) * BS_LD + wn * 64 + nt * 8 + g;
                unsigned b0 = __float_as_uint(bp[0]);
                unsigned b1 = __float_as_uint(bp[4 * BS_LD]);
                mma_tf32(acc[0][nt], a[0], b0, b1);
                mma_tf32(acc[1][nt], a[1], b0, b1);
            }
        }
        __syncthreads();
    }

    #pragma unroll
    for (int mt = 0; mt < 2; mt++) {
        int r = row0 + wm * 32 + mt * 16 + g;
        #pragma unroll
        for (int nt = 0; nt < 8; nt++) {
            int c = col0 + wn * 64 + nt * 8 + 2 * t;
            float2 v0 = make_float2(acc[mt][nt][0], acc[mt][nt][1]);
            float2 v1 = make_float2(acc[mt][nt][2], acc[mt][nt][3]);
            if (bias) {
                float bx = bias[c], by = bias[c + 1];
                v0.x += bx; v0.y += by;
                v1.x += bx; v1.y += by;
            }
            *(float2*)&C[(size_t)r * DM + c]       = v0;
            *(float2*)&C[(size_t)(r + 8) * DM + c] = v1;
        }
    }
}

// ============================================================================
// Flash attention (causal, tf32 mma). 128 q-rows/CTA, KT=64 per iter.
// 8 warps, warp owns 16 q-rows. Output is pre-rounded to tf32 for out-proj.
// ============================================================================
#define FS_LD 68
#define FLASH_SMEM ((128 * FS_LD + 64 * FS_LD + 64 * FS_LD + 128 * FS_LD) * (int)sizeof(float))

__global__ __launch_bounds__(256) void flash_tf32(
    const float* __restrict__ Q, const float* __restrict__ K,
    const float* __restrict__ V, float* __restrict__ O)
{
    extern __shared__ float smf[];
    float* Qs = smf;                    // [128][68]  (q, d)
    float* Ks = Qs + 128 * FS_LD;       // [64][68]   (key, d)
    float* Vs = Ks + 64 * FS_LD;        // [64][68]   (d, key)  transposed
    float* Ps = Vs + 64 * FS_LD;        // [128][68]  (q, key)

    const int tid = threadIdx.x;
    const int lane = tid & 31, wid = tid >> 5;
    const int g = lane >> 2, t = lane & 3;
    const int q0 = blockIdx.x * 128;
    const int h = blockIdx.y, b = blockIdx.z;
    const size_t base = ((size_t)b * CTX) * DM + h * HD;
    const float scale = 0.125f;

    // load Q tile (scaled + rounded)
    #pragma unroll
    for (int i = 0; i < 8; i++) {
        int idx = tid + i * 256;
        int q = idx >> 4, c4 = idx & 15;
        float4 v = *(const float4*)(Q + base + (size_t)(q0 + q) * DM + 4 * c4);
        v.x = rna(v.x * scale); v.y = rna(v.y * scale);
        v.z = rna(v.z * scale); v.w = rna(v.w * scale);
        *(float4*)(Qs + q * FS_LD + 4 * c4) = v;
    }

    float m0 = -INFINITY, m1 = -INFINITY, l0 = 0.f, l1 = 0.f;
    float o[8][4];
    #pragma unroll
    for (int dt = 0; dt < 8; dt++)
        #pragma unroll
        for (int r = 0; r < 4; r++) o[dt][r] = 0.f;

    const int nkv = q0 / 64 + 2;
    for (int tkv = 0; tkv < nkv; ++tkv) {
        const int kb = tkv * 64;

        // load K (row-major, rounded) and V (transposed d-major, rounded)
        #pragma unroll
        for (int i = 0; i < 4; i++) {
            int idx = tid + i * 256;
            int kk = idx >> 4, c4 = idx & 15;
            float4 v = *(const float4*)(K + base + (size_t)(kb + kk) * DM + 4 * c4);
            v.x = rna(v.x); v.y = rna(v.y); v.z = rna(v.z); v.w = rna(v.w);
            *(float4*)(Ks + kk * FS_LD + 4 * c4) = v;
            float4 w = *(const float4*)(V + base + (size_t)(kb + kk) * DM + 4 * c4);
            Vs[(4 * c4 + 0) * FS_LD + kk] = rna(w.x);
            Vs[(4 * c4 + 1) * FS_LD + kk] = rna(w.y);
            Vs[(4 * c4 + 2) * FS_LD + kk] = rna(w.z);
            Vs[(4 * c4 + 3) * FS_LD + kk] = rna(w.w);
        }
        __syncthreads();

        // S = Q @ K^T   (warp: 16 x 64)
        float s[8][4];
        #pragma unroll
        for (int nt = 0; nt < 8; nt++)
            #pragma unroll
            for (int r = 0; r < 4; r++) s[nt][r] = 0.f;

        #pragma unroll
        for (int ks = 0; ks < 8; ks++) {
            unsigned a[4];
            const float* qp = Qs + (wid * 16 + g) * FS_LD + ks * 8 + t;
            a[0] = __float_as_uint(qp[0]);
            a[1] = __float_as_uint(qp[8 * FS_LD]);
            a[2] = __float_as_uint(qp[4]);
            a[3] = __float_as_uint(qp[8 * FS_LD + 4]);
            #pragma unroll
            for (int nt = 0; nt < 8; nt++) {
                const float* kp = Ks + (nt * 8 + g) * FS_LD + ks * 8 + t;
                mma_tf32(s[nt], a, __float_as_uint(kp[0]), __float_as_uint(kp[4]));
            }
        }

        const int r0 = q0 + wid * 16 + g;
        const int r1 = r0 + 8;

        // causal mask (only diagonal-crossing tiles)
        if (kb + 63 > q0) {
            #pragma unroll
            for (int nt = 0; nt < 8; nt++) {
                #pragma unroll
                for (int j = 0; j < 2; j++) {
                    int key = kb + nt * 8 + 2 * t + j;
                    if (key > r0) s[nt][j]     = -1e30f;
                    if (key > r1) s[nt][2 + j] = -1e30f;
                }
            }
        }

        // online softmax
        float rm0 = -1e30f, rm1 = -1e30f;
        #pragma unroll
        for (int nt = 0; nt < 8; nt++) {
            rm0 = fmaxf(rm0, fmaxf(s[nt][0], s[nt][1]));
            rm1 = fmaxf(rm1, fmaxf(s[nt][2], s[nt][3]));
        }
        rm0 = fmaxf(rm0, __shfl_xor_sync(0xffffffffu, rm0, 1));
        rm0 = fmaxf(rm0, __shfl_xor_sync(0xffffffffu, rm0, 2));
        rm1 = fmaxf(rm1, __shfl_xor_sync(0xffffffffu, rm1, 1));
        rm1 = fmaxf(rm1, __shfl_xor_sync(0xffffffffu, rm1, 2));

        float mn0 = fmaxf(m0, rm0), mn1 = fmaxf(m1, rm1);
        float c0 = __expf(m0 - mn0), c1 = __expf(m1 - mn1);
        float rs0 = 0.f, rs1 = 0.f;
        #pragma unroll
        for (int nt = 0; nt < 8; nt++) {
            s[nt][0] = __expf(s[nt][0] - mn0);
            s[nt][1] = __expf(s[nt][1] - mn0);
            s[nt][2] = __expf(s[nt][2] - mn1);
            s[nt][3] = __expf(s[nt][3] - mn1);
            rs0 += s[nt][0] + s[nt][1];
            rs1 += s[nt][2] + s[nt][3];
        }
        rs0 += __shfl_xor_sync(0xffffffffu, rs0, 1);
        rs0 += __shfl_xor_sync(0xffffffffu, rs0, 2);
        rs1 += __shfl_xor_sync(0xffffffffu, rs1, 1);
        rs1 += __shfl_xor_sync(0xffffffffu, rs1, 2);

        l0 = l0 * c0 + rs0; m0 = mn0;
        l1 = l1 * c1 + rs1; m1 = mn1;
        #pragma unroll
        for (int dt = 0; dt < 8; dt++) {
            o[dt][0] *= c0; o[dt][1] *= c0;
            o[dt][2] *= c1; o[dt][3] *= c1;
        }

        // write P (rounded) to smem
        #pragma unroll
        for (int nt = 0; nt < 8; nt++) {
            float2 p0 = make_float2(rna(s[nt][0]), rna(s[nt][1]));
            float2 p1 = make_float2(rna(s[nt][2]), rna(s[nt][3]));
            *(float2*)(Ps + (wid * 16 + g) * FS_LD + nt * 8 + 2 * t)     = p0;
            *(float2*)(Ps + (wid * 16 + g + 8) * FS_LD + nt * 8 + 2 * t) = p1;
        }
        __syncwarp();

        // O += P @ V
        #pragma unroll
        for (int ks = 0; ks < 8; ks++) {
            unsigned a[4];
            const float* pp = Ps + (wid * 16 + g) * FS_LD + ks * 8 + t;
            a[0] = __float_as_uint(pp[0]);
            a[1] = __float_as_uint(pp[8 * FS_LD]);
            a[2] = __float_as_uint(pp[4]);
            a[3] = __float_as_uint(pp[8 * FS_LD + 4]);
            #pragma unroll
            for (int dt = 0; dt < 8; dt++) {
                const float* vp = Vs + (dt * 8 + g) * FS_LD + ks * 8 + t;
                mma_tf32(o[dt], a, __float_as_uint(vp[0]), __float_as_uint(vp[4]));
            }
        }
        __syncthreads();
    }

    // epilogue: normalize, round to tf32 (feeds out-proj GEMM), store ctx
    float i0 = 1.f / l0, i1 = 1.f / l1;
    const int r0 = q0 + wid * 16 + g;
    #pragma unroll
    for (int dt = 0; dt < 8; dt++) {
        int c = dt * 8 + 2 * t;
        float2 v0 = make_float2(rna(o[dt][0] * i0), rna(o[dt][1] * i0));
        float2 v1 = make_float2(rna(o[dt][2] * i1), rna(o[dt][3] * i1));
        *(float2*)(O + base + (size_t)r0 * DM + c)       = v0;
        *(float2*)(O + base + (size_t)(r0 + 8) * DM + c) = v1;
    }
}

// ============================================================================
// launch
// ============================================================================
extern "C" void kernel_launch(void* const* d_in, const int* in_sizes, int n_in,
                              void* d_out, int out_size)
{
    const float* x  = (const float*)d_in[0];
    const float* Wq = (const float*)d_in[1];
    const float* Wk = (const float*)d_in[2];
    const float* Wv = (const float*)d_in[3];
    const float* Wo = (const float*)d_in[4];
    const float* bo = (const float*)d_in[5];
    float* out = (float*)d_out;

    float *Qp, *Kp, *Vp, *Cp, *Xr, *Wr;
    cudaGetSymbolAddress((void**)&Qp, g_Q);
    cudaGetSymbolAddress((void**)&Kp, g_K);
    cudaGetSymbolAddress((void**)&Vp, g_V);
    cudaGetSymbolAddress((void**)&Cp, g_C);
    cudaGetSymbolAddress((void**)&Xr, g_Xr);
    cudaGetSymbolAddress((void**)&Wr, g_Wr);

    cudaFuncSetAttribute(gemm_tf32, cudaFuncAttributeMaxDynamicSharedMemorySize, GEMM_SMEM);
    cudaFuncSetAttribute(flash_tf32, cudaFuncAttributeMaxDynamicSharedMemorySize, FLASH_SMEM);

    // pre-round x and weights to tf32 (rna)
    const int NX4 = BT * DM / 4;   // 1048576
    const int NW4 = DM * DM / 4;   // 262144
    round_k<<<NX4 / 256, 256>>>((const float4*)x,  (float4*)Xr, NX4);
    round_k<<<NW4 / 256, 256>>>((const float4*)Wq, (float4*)(Wr + 0 * DM * DM), NW4);
    round_k<<<NW4 / 256, 256>>>((const float4*)Wk, (float4*)(Wr + 1 * DM * DM), NW4);
    round_k<<<NW4 / 256, 256>>>((const float4*)Wv, (float4*)(Wr + 2 * DM * DM), NW4);
    round_k<<<NW4 / 256, 256>>>((const float4*)Wo, (float4*)(Wr + 3 * DM * DM), NW4);

    dim3 ggrid(DM / 128, BT / 128);   // (8, 32)
    gemm_tf32<<<ggrid, 256, GEMM_SMEM>>>(Xr, Wr + 0 * DM * DM, nullptr, Qp);
    gemm_tf32<<<ggrid, 256, GEMM_SMEM>>>(Xr, Wr + 1 * DM * DM, nullptr, Kp);
    gemm_tf32<<<ggrid, 256, GEMM_SMEM>>>(Xr, Wr + 2 * DM * DM, nullptr, Vp);

    dim3 fgrid(CTX / 128, NH, BATCH);  // (16, 16, 2)
    flash_tf32<<<fgrid, 256, FLASH_SMEM>>>(Qp, Kp, Vp, Cp);

    gemm_tf32<<<ggrid, 256, GEMM_SMEM>>>(Cp, Wr + 3 * DM * DM, bo, out);
}